// round 1
// baseline (speedup 1.0000x reference)
#include <cuda_runtime.h>

#define N 2048
#define DIM 64
#define NN (N*N)
#define JSPLIT 8
#define ROWS_PB 64
#define JT 32
// math.log(2048) in double, rounded to float at use site
#define LOG_N 7.624618986159398f

// ---------------- scratch (device globals; no allocation allowed) ----------
__device__ float g_pd[NN];                 // pairwise squared distances (16MB)
__device__ float g_r2[N];                  // ||x_i||^2
__device__ float g_t[N*DIM];               // t_j = D_j mu
__device__ float g_c[N*DIM];               // c_j = x_j / r2_j
__device__ float g_part[JSPLIT][N][DIM];   // partial A accumulators (4MB)
__device__ float g_hh;                     // kernel bandwidth hh = h + 1e-6
__device__ unsigned g_hist[2][256];        // radix-select histograms (2 ranks)
__device__ unsigned g_prefix[2];
__device__ unsigned g_rank[2];

// ---------------- 1) per-row stats: r2, t = D mu, c = x/r2 ----------------
__global__ void k_rowstats(const float* __restrict__ x, const float* __restrict__ mu) {
    int row  = blockIdx.x;
    int lane = threadIdx.x;  // 32 threads, each owns dims lane and lane+32
    float x0 = x[row*DIM + lane];
    float x1 = x[row*DIM + lane + 32];
    float m0 = mu[lane];
    float m1 = mu[lane + 32];
    float r2p = x0*x0 + x1*x1;
    float xmp = x0*m0 + x1*m1;
    #pragma unroll
    for (int o = 16; o > 0; o >>= 1) {
        r2p += __shfl_xor_sync(0xFFFFFFFFu, r2p, o);
        xmp += __shfl_xor_sync(0xFFFFFFFFu, xmp, o);
    }
    float inv = 1.0f / r2p;
    g_t[row*DIM + lane]      = m0 - x0 * xmp * inv;
    g_t[row*DIM + lane + 32] = m1 - x1 * xmp * inv;
    g_c[row*DIM + lane]      = x0 * inv;
    g_c[row*DIM + lane + 32] = x1 * inv;
    if (lane == 0) g_r2[row] = r2p;
}

// ---------------- 2) Gram -> pd = max(r2_i + r2_j - 2 x_i.x_j, 0) ----------
__global__ __launch_bounds__(256) void k_gram(const float* __restrict__ x) {
    __shared__ float sA[64][65];
    __shared__ float sB[64][65];
    int iBase = blockIdx.y * 64;
    int jBase = blockIdx.x * 64;
    int t = threadIdx.y * 16 + threadIdx.x;
    for (int e = t; e < 64*64; e += 256) {
        int i = e >> 6, d = e & 63;
        sA[i][d] = x[(iBase + i)*DIM + d];
        sB[i][d] = x[(jBase + i)*DIM + d];
    }
    __syncthreads();
    int i0 = threadIdx.y * 4, j0 = threadIdx.x * 4;
    float acc[4][4] = {};
    #pragma unroll 8
    for (int d = 0; d < 64; d++) {
        float a[4], b[4];
        #pragma unroll
        for (int r = 0; r < 4; r++) a[r] = sA[i0 + r][d];
        #pragma unroll
        for (int c = 0; c < 4; c++) b[c] = sB[j0 + c][d];
        #pragma unroll
        for (int r = 0; r < 4; r++)
            #pragma unroll
            for (int c = 0; c < 4; c++)
                acc[r][c] = fmaf(a[r], b[c], acc[r][c]);
    }
    float rj[4];
    #pragma unroll
    for (int c = 0; c < 4; c++) rj[c] = g_r2[jBase + j0 + c];
    #pragma unroll
    for (int r = 0; r < 4; r++) {
        int ig = iBase + i0 + r;
        float ri = g_r2[ig];
        float4 o;
        o.x = fmaxf(ri + rj[0] - 2.0f*acc[r][0], 0.0f);
        o.y = fmaxf(ri + rj[1] - 2.0f*acc[r][1], 0.0f);
        o.z = fmaxf(ri + rj[2] - 2.0f*acc[r][2], 0.0f);
        o.w = fmaxf(ri + rj[3] - 2.0f*acc[r][3], 0.0f);
        *(float4*)&g_pd[(size_t)ig * N + jBase + j0] = o;
    }
}

// ---------------- 3) exact median: dual radix select --------------------
__global__ void k_msel_init() {
    int t = threadIdx.x;  // 256 threads
    g_hist[0][t] = 0u;
    g_hist[1][t] = 0u;
    if (t < 2) g_prefix[t] = 0u;
    if (t == 0) { g_rank[0] = NN/2 - 1; g_rank[1] = NN/2; }
}

__global__ __launch_bounds__(256) void k_hist(int level) {
    __shared__ unsigned sh[2][256];
    int t = threadIdx.x;
    sh[0][t] = 0u; sh[1][t] = 0u;
    __syncthreads();
    unsigned mask = (level == 0) ? 0u : (0xFFFFFFFFu << (32 - 8*level));
    unsigned p0 = g_prefix[0], p1 = g_prefix[1];
    int shift = 24 - 8*level;
    long long stride = (long long)gridDim.x * 256;
    for (long long idx = (long long)blockIdx.x * 256 + t; idx < NN; idx += stride) {
        unsigned bits = __float_as_uint(g_pd[idx]);
        unsigned b = (bits >> shift) & 255u;
        if ((bits & mask) == p0) atomicAdd(&sh[0][b], 1u);
        if ((bits & mask) == p1) atomicAdd(&sh[1][b], 1u);
    }
    __syncthreads();
    if (sh[0][t]) atomicAdd(&g_hist[0][t], sh[0][t]);
    if (sh[1][t]) atomicAdd(&g_hist[1][t], sh[1][t]);
}

__global__ void k_scan(int level) {
    int shift = 24 - 8*level;
    for (int r = 0; r < 2; r++) {
        unsigned rank = g_rank[r];
        unsigned long long cum = 0;
        unsigned sel = 255u;
        for (int b = 0; b < 256; b++) {
            unsigned c = g_hist[r][b];
            if (cum + c > (unsigned long long)rank) { sel = (unsigned)b; g_rank[r] = rank - (unsigned)cum; break; }
            cum += c;
        }
        g_prefix[r] |= sel << shift;
    }
    for (int i = 0; i < 256; i++) { g_hist[0][i] = 0u; g_hist[1][i] = 0u; }
    if (level == 3) {
        float v0 = __uint_as_float(g_prefix[0]);
        float v1 = __uint_as_float(g_prefix[1]);
        float h = (v0 + v1) * 0.5f / LOG_N;
        g_hh = h + 1e-6f;
    }
}

// ---------------- 4) main fused reduction ------------------------------
// A_i += sum_j k_ij * t_j  -  k_ij*(2*dot_ij/hh + 63) * c_j
__global__ __launch_bounds__(256) void k_main() {
    __shared__ float swt[ROWS_PB][JT + 1];
    __shared__ float swc[ROWS_PB][JT + 1];
    __shared__ float sT[JT][DIM];
    __shared__ float sC[JT][DIM];
    __shared__ float sr2i[ROWS_PB];
    __shared__ float sr2j[JT];

    int rowBase = blockIdx.x * ROWS_PB;
    int jBase0  = blockIdx.y * (N / JSPLIT);
    int t = threadIdx.y * 16 + threadIdx.x;
    const float hh = g_hh;
    const float inv_hh = 1.0f / hh;
    const float two_inv = 2.0f * inv_hh;

    if (t < ROWS_PB) sr2i[t] = g_r2[rowBase + t];

    float acc[4][4] = {};
    int ty4 = threadIdx.y * 4, tx4 = threadIdx.x * 4;

    for (int jt = 0; jt < (N / JSPLIT) / JT; jt++) {
        int jBase = jBase0 + jt * JT;
        __syncthreads();  // previous-iter consumers done (also covers sr2i on iter 0)
        if (t < JT) sr2j[t] = g_r2[jBase + t];
        for (int e = t; e < JT * DIM; e += 256) {
            int jj = e >> 6, d = e & 63;
            sT[jj][d] = g_t[(jBase + jj)*DIM + d];
            sC[jj][d] = g_c[(jBase + jj)*DIM + d];
        }
        __syncthreads();
        // phase A: weights
        for (int e = t; e < ROWS_PB * JT; e += 256) {
            int i = e / JT, jj = e % JT;
            float pdv = g_pd[(size_t)(rowBase + i) * N + jBase + jj];
            float k = __expf(-pdv * inv_hh);
            float dot = 0.5f * (sr2i[i] + sr2j[jj] - pdv);
            swt[i][jj] = k;
            swc[i][jj] = k * (two_inv * dot + (float)(DIM - 1));
        }
        __syncthreads();
        // phase B: rank-1 accumulate
        #pragma unroll 4
        for (int jj = 0; jj < JT; jj++) {
            float4 tv = *(const float4*)&sT[jj][tx4];
            float4 cv = *(const float4*)&sC[jj][tx4];
            #pragma unroll
            for (int r = 0; r < 4; r++) {
                float wt = swt[ty4 + r][jj];
                float wc = swc[ty4 + r][jj];
                acc[r][0] = fmaf(wt, tv.x, fmaf(-wc, cv.x, acc[r][0]));
                acc[r][1] = fmaf(wt, tv.y, fmaf(-wc, cv.y, acc[r][1]));
                acc[r][2] = fmaf(wt, tv.z, fmaf(-wc, cv.z, acc[r][2]));
                acc[r][3] = fmaf(wt, tv.w, fmaf(-wc, cv.w, acc[r][3]));
            }
        }
    }
    #pragma unroll
    for (int r = 0; r < 4; r++) {
        float4 o = make_float4(acc[r][0], acc[r][1], acc[r][2], acc[r][3]);
        *(float4*)&g_part[blockIdx.y][rowBase + ty4 + r][tx4] = o;
    }
}

// ---------------- 5) epilogue: projector + step -------------------------
__global__ void k_epilogue(const float* __restrict__ x, float* __restrict__ out) {
    int row = blockIdx.x;
    int lane = threadIdx.x;  // 32
    float a0 = 0.0f, a1 = 0.0f;
    #pragma unroll
    for (int s = 0; s < JSPLIT; s++) {
        a0 += g_part[s][row][lane];
        a1 += g_part[s][row][lane + 32];
    }
    float x0 = x[row*DIM + lane];
    float x1 = x[row*DIM + lane + 32];
    float xa = x0*a0 + x1*a1;
    #pragma unroll
    for (int o = 16; o > 0; o >>= 1) xa += __shfl_xor_sync(0xFFFFFFFFu, xa, o);
    float r2 = g_r2[row];
    float coef = (xa + (float)(DIM - 1)) / r2;  // (x.A + 63)/r2
    float gr0 = a0 - x0 * coef;
    float gr1 = a1 - x1 * coef;
    const float sc = 0.1f / (float)N;
    float d0 = gr0 * sc;
    float d1 = gr1 * sc;
    d0 = fminf(fmaxf(d0, -1000.0f), 1000.0f);
    d1 = fminf(fmaxf(d1, -1000.0f), 1000.0f);
    out[row*DIM + lane]      = x0 + d0;
    out[row*DIM + lane + 32] = x1 + d1;
}

// ---------------- launch -----------------------------------------------
extern "C" void kernel_launch(void* const* d_in, const int* in_sizes, int n_in,
                              void* d_out, int out_size) {
    const float* x  = (const float*)d_in[0];   // particle [2048, 64]
    const float* mu = (const float*)d_in[1];   // mu [64]
    float* out = (float*)d_out;

    k_rowstats<<<N, 32>>>(x, mu);
    k_gram<<<dim3(N/64, N/64), dim3(16, 16)>>>(x);
    k_msel_init<<<1, 256>>>();
    for (int level = 0; level < 4; level++) {
        k_hist<<<1024, 256>>>(level);
        k_scan<<<1, 1>>>(level);
    }
    k_main<<<dim3(N/ROWS_PB, JSPLIT), dim3(16, 16)>>>();
    k_epilogue<<<N, 32>>>(x, out);
}

// round 6
// speedup vs baseline: 1.4697x; 1.4697x over previous
#include <cuda_runtime.h>

#define N 2048
#define DIM 64
#define NN (N*N)
#define JSPLIT 8
#define ROWS_PB 64
#define JT 32
#define LOG_N 7.624618986159398f

// ---------------- scratch (device globals; no allocation allowed) ----------
__device__ float g_pd[NN];                 // pairwise squared distances (16MB)
__device__ float g_r2[N];                  // ||x_i||^2
__device__ float g_t[N*DIM];               // t_j = D_j mu
__device__ float g_c[N*DIM];               // c_j = x_j / r2_j
__device__ float g_part[JSPLIT][N][DIM];   // partial A accumulators (4MB)
__device__ float g_hh;                     // kernel bandwidth hh = h + 1e-6
__device__ unsigned g_hist[2][256];        // radix-select histograms (2 ranks)
__device__ unsigned g_prefix[2];
__device__ unsigned g_rank[2];

// warp-aggregated shared-mem histogram add (full warp must participate)
__device__ __forceinline__ void hist_add(unsigned* sh, unsigned bin, unsigned lane) {
    unsigned m = __match_any_sync(0xFFFFFFFFu, bin);
    if ((unsigned)(__ffs(m) - 1) == lane)
        atomicAdd(&sh[bin], (unsigned)__popc(m));
}

// ---------------- 1) per-row stats: r2, t = D mu, c = x/r2 ----------------
__global__ void k_rowstats(const float* __restrict__ x, const float* __restrict__ mu) {
    int row  = blockIdx.x;
    int lane = threadIdx.x;  // 32 threads, each owns dims lane and lane+32
    float x0 = x[row*DIM + lane];
    float x1 = x[row*DIM + lane + 32];
    float m0 = mu[lane];
    float m1 = mu[lane + 32];
    float r2p = x0*x0 + x1*x1;
    float xmp = x0*m0 + x1*m1;
    #pragma unroll
    for (int o = 16; o > 0; o >>= 1) {
        r2p += __shfl_xor_sync(0xFFFFFFFFu, r2p, o);
        xmp += __shfl_xor_sync(0xFFFFFFFFu, xmp, o);
    }
    float inv = 1.0f / r2p;
    g_t[row*DIM + lane]      = m0 - x0 * xmp * inv;
    g_t[row*DIM + lane + 32] = m1 - x1 * xmp * inv;
    g_c[row*DIM + lane]      = x0 * inv;
    g_c[row*DIM + lane + 32] = x1 * inv;
    if (lane == 0) g_r2[row] = r2p;
}

// ---------------- 2) Gram -> pd, with fused level-0 radix histogram --------
__global__ __launch_bounds__(256) void k_gram(const float* __restrict__ x) {
    __shared__ float sA[64][65];
    __shared__ float sB[64][65];
    __shared__ unsigned shist[256];
    int iBase = blockIdx.y * 64;
    int jBase = blockIdx.x * 64;
    int t = threadIdx.y * 16 + threadIdx.x;
    unsigned lane = (unsigned)t & 31u;
    shist[t] = 0u;
    for (int e = t; e < 64*64; e += 256) {
        int i = e >> 6, d = e & 63;
        sA[i][d] = x[(iBase + i)*DIM + d];
        sB[i][d] = x[(jBase + i)*DIM + d];
    }
    __syncthreads();
    int i0 = threadIdx.y * 4, j0 = threadIdx.x * 4;
    float acc[4][4] = {};
    #pragma unroll 8
    for (int d = 0; d < 64; d++) {
        float a[4], b[4];
        #pragma unroll
        for (int r = 0; r < 4; r++) a[r] = sA[i0 + r][d];
        #pragma unroll
        for (int c = 0; c < 4; c++) b[c] = sB[j0 + c][d];
        #pragma unroll
        for (int r = 0; r < 4; r++)
            #pragma unroll
            for (int c = 0; c < 4; c++)
                acc[r][c] = fmaf(a[r], b[c], acc[r][c]);
    }
    float rj[4];
    #pragma unroll
    for (int c = 0; c < 4; c++) rj[c] = g_r2[jBase + j0 + c];
    #pragma unroll
    for (int r = 0; r < 4; r++) {
        int ig = iBase + i0 + r;
        float ri = g_r2[ig];
        float4 o;
        o.x = fmaxf(ri + rj[0] - 2.0f*acc[r][0], 0.0f);
        o.y = fmaxf(ri + rj[1] - 2.0f*acc[r][1], 0.0f);
        o.z = fmaxf(ri + rj[2] - 2.0f*acc[r][2], 0.0f);
        o.w = fmaxf(ri + rj[3] - 2.0f*acc[r][3], 0.0f);
        *(float4*)&g_pd[(size_t)ig * N + jBase + j0] = o;
        // fused level-0 histogram (top byte of float bits)
        hist_add(shist, __float_as_uint(o.x) >> 24, lane);
        hist_add(shist, __float_as_uint(o.y) >> 24, lane);
        hist_add(shist, __float_as_uint(o.z) >> 24, lane);
        hist_add(shist, __float_as_uint(o.w) >> 24, lane);
    }
    __syncthreads();
    unsigned hv = shist[t];
    if (hv) {
        atomicAdd(&g_hist[0][t], hv);   // level-0 prefixes for both ranks are
        atomicAdd(&g_hist[1][t], hv);   // identical (empty) -> same histogram
    }
}

// ---------------- 3) exact median: dual radix select --------------------
__global__ void k_msel_init() {
    int t = threadIdx.x;  // 256 threads
    g_hist[0][t] = 0u;
    g_hist[1][t] = 0u;
    if (t < 2) g_prefix[t] = 0u;
    if (t == 0) { g_rank[0] = NN/2 - 1; g_rank[1] = NN/2; }
}

// float4 loads + warp-aggregated shared atomics (levels 1..3)
__global__ __launch_bounds__(256) void k_hist(int level) {
    __shared__ unsigned sh[2][256];
    int t = threadIdx.x;
    unsigned lane = (unsigned)t & 31u;
    sh[0][t] = 0u; sh[1][t] = 0u;
    __syncthreads();
    unsigned mask = 0xFFFFFFFFu << (32 - 8*level);
    unsigned p0 = g_prefix[0], p1 = g_prefix[1];
    bool same = (p0 == p1);
    int shift = 24 - 8*level;
    const float4* pd4 = (const float4*)g_pd;
    int stride = gridDim.x * 256;
    // NN/4 = 1,048,576 ; grid 2048*256 = 524,288 -> exactly 2 full iterations,
    // every warp fully active (ballot/match safe).
    for (int idx = blockIdx.x * 256 + t; idx < NN/4; idx += stride) {
        float4 v = pd4[idx];
        unsigned bw[4];
        bw[0] = __float_as_uint(v.x); bw[1] = __float_as_uint(v.y);
        bw[2] = __float_as_uint(v.z); bw[3] = __float_as_uint(v.w);
        #pragma unroll
        for (int q = 0; q < 4; q++) {
            unsigned bits = bw[q];
            unsigned bin = (bits >> shift) & 255u;
            bool c0 = (bits & mask) == p0;
            unsigned a0 = __ballot_sync(0xFFFFFFFFu, c0);
            if (c0) {
                unsigned m = __match_any_sync(a0, bin);
                if ((unsigned)(__ffs(m) - 1) == lane)
                    atomicAdd(&sh[0][bin], (unsigned)__popc(m));
            }
            if (!same) {
                bool c1 = (bits & mask) == p1;
                unsigned a1 = __ballot_sync(0xFFFFFFFFu, c1);
                if (c1) {
                    unsigned m = __match_any_sync(a1, bin);
                    if ((unsigned)(__ffs(m) - 1) == lane)
                        atomicAdd(&sh[1][bin], (unsigned)__popc(m));
                }
            }
        }
    }
    __syncthreads();
    unsigned h0 = sh[0][t];
    unsigned h1 = same ? h0 : sh[1][t];
    if (h0) atomicAdd(&g_hist[0][t], h0);
    if (h1) atomicAdd(&g_hist[1][t], h1);
}

// parallel scan + bucket select (256 threads)
__global__ void k_scan(int level) {
    __shared__ unsigned e0[256], e1[256];
    int t = threadIdx.x;
    unsigned v0 = g_hist[0][t];
    unsigned v1 = g_hist[1][t];
    e0[t] = v0; e1[t] = v1;
    __syncthreads();
    // Hillis-Steele inclusive scan
    #pragma unroll
    for (int off = 1; off < 256; off <<= 1) {
        unsigned a0 = (t >= off) ? e0[t - off] : 0u;
        unsigned a1 = (t >= off) ? e1[t - off] : 0u;
        __syncthreads();
        e0[t] += a0; e1[t] += a1;
        __syncthreads();
    }
    unsigned inc0 = e0[t], inc1 = e1[t];
    unsigned exc0 = inc0 - v0, exc1 = inc1 - v1;
    int shift = 24 - 8*level;
    unsigned r0 = g_rank[0], r1 = g_rank[1];
    if (exc0 <= r0 && r0 < inc0) {        // exactly one thread matches
        g_prefix[0] |= ((unsigned)t) << shift;
        g_rank[0] = r0 - exc0;
    }
    if (exc1 <= r1 && r1 < inc1) {
        g_prefix[1] |= ((unsigned)t) << shift;
        g_rank[1] = r1 - exc1;
    }
    // clear for next level
    g_hist[0][t] = 0u; g_hist[1][t] = 0u;
    if (level == 3) {
        __syncthreads();  // make g_prefix writes (same block) visible
        if (t == 0) {
            float va = __uint_as_float(g_prefix[0]);
            float vb = __uint_as_float(g_prefix[1]);
            float h = (va + vb) * 0.5f / LOG_N;
            g_hh = h + 1e-6f;
        }
    }
}

// ---------------- 4) main fused reduction ------------------------------
// A_i += sum_j k_ij * t_j  -  k_ij*(2*dot_ij/hh + 63) * c_j
__global__ __launch_bounds__(256) void k_main() {
    __shared__ float swt[ROWS_PB][JT + 1];
    __shared__ float swc[ROWS_PB][JT + 1];
    __shared__ float sT[JT][DIM];
    __shared__ float sC[JT][DIM];
    __shared__ float sr2i[ROWS_PB];
    __shared__ float sr2j[JT];

    int rowBase = blockIdx.x * ROWS_PB;
    int jBase0  = blockIdx.y * (N / JSPLIT);
    int t = threadIdx.y * 16 + threadIdx.x;
    const float hh = g_hh;
    const float inv_hh = 1.0f / hh;
    const float two_inv = 2.0f * inv_hh;

    if (t < ROWS_PB) sr2i[t] = g_r2[rowBase + t];

    float acc[4][4] = {};
    int ty4 = threadIdx.y * 4, tx4 = threadIdx.x * 4;

    for (int jt = 0; jt < (N / JSPLIT) / JT; jt++) {
        int jBase = jBase0 + jt * JT;
        __syncthreads();
        if (t < JT) sr2j[t] = g_r2[jBase + t];
        for (int e = t; e < JT * DIM; e += 256) {
            int jj = e >> 6, d = e & 63;
            sT[jj][d] = g_t[(jBase + jj)*DIM + d];
            sC[jj][d] = g_c[(jBase + jj)*DIM + d];
        }
        __syncthreads();
        // phase A: weights
        for (int e = t; e < ROWS_PB * JT; e += 256) {
            int i = e / JT, jj = e % JT;
            float pdv = g_pd[(size_t)(rowBase + i) * N + jBase + jj];
            float k = __expf(-pdv * inv_hh);
            float dot = 0.5f * (sr2i[i] + sr2j[jj] - pdv);
            swt[i][jj] = k;
            swc[i][jj] = k * (two_inv * dot + (float)(DIM - 1));
        }
        __syncthreads();
        // phase B: rank-1 accumulate
        #pragma unroll 4
        for (int jj = 0; jj < JT; jj++) {
            float4 tv = *(const float4*)&sT[jj][tx4];
            float4 cv = *(const float4*)&sC[jj][tx4];
            #pragma unroll
            for (int r = 0; r < 4; r++) {
                float wt = swt[ty4 + r][jj];
                float wc = swc[ty4 + r][jj];
                acc[r][0] = fmaf(wt, tv.x, fmaf(-wc, cv.x, acc[r][0]));
                acc[r][1] = fmaf(wt, tv.y, fmaf(-wc, cv.y, acc[r][1]));
                acc[r][2] = fmaf(wt, tv.z, fmaf(-wc, cv.z, acc[r][2]));
                acc[r][3] = fmaf(wt, tv.w, fmaf(-wc, cv.w, acc[r][3]));
            }
        }
    }
    #pragma unroll
    for (int r = 0; r < 4; r++) {
        float4 o = make_float4(acc[r][0], acc[r][1], acc[r][2], acc[r][3]);
        *(float4*)&g_part[blockIdx.y][rowBase + ty4 + r][tx4] = o;
    }
}

// ---------------- 5) epilogue: projector + step -------------------------
__global__ void k_epilogue(const float* __restrict__ x, float* __restrict__ out) {
    int row = blockIdx.x;
    int lane = threadIdx.x;  // 32
    float a0 = 0.0f, a1 = 0.0f;
    #pragma unroll
    for (int s = 0; s < JSPLIT; s++) {
        a0 += g_part[s][row][lane];
        a1 += g_part[s][row][lane + 32];
    }
    float x0 = x[row*DIM + lane];
    float x1 = x[row*DIM + lane + 32];
    float xa = x0*a0 + x1*a1;
    #pragma unroll
    for (int o = 16; o > 0; o >>= 1) xa += __shfl_xor_sync(0xFFFFFFFFu, xa, o);
    float r2 = g_r2[row];
    float coef = (xa + (float)(DIM - 1)) / r2;  // (x.A + 63)/r2
    float gr0 = a0 - x0 * coef;
    float gr1 = a1 - x1 * coef;
    const float sc = 0.1f / (float)N;
    float d0 = gr0 * sc;
    float d1 = gr1 * sc;
    d0 = fminf(fmaxf(d0, -1000.0f), 1000.0f);
    d1 = fminf(fmaxf(d1, -1000.0f), 1000.0f);
    out[row*DIM + lane]      = x0 + d0;
    out[row*DIM + lane + 32] = x1 + d1;
}

// ---------------- launch -----------------------------------------------
extern "C" void kernel_launch(void* const* d_in, const int* in_sizes, int n_in,
                              void* d_out, int out_size) {
    const float* x  = (const float*)d_in[0];   // particle [2048, 64]
    const float* mu = (const float*)d_in[1];   // mu [64]
    float* out = (float*)d_out;

    k_rowstats<<<N, 32>>>(x, mu);
    k_msel_init<<<1, 256>>>();
    k_gram<<<dim3(N/64, N/64), dim3(16, 16)>>>(x);   // writes pd + level-0 hist
    k_scan<<<1, 256>>>(0);
    for (int level = 1; level < 4; level++) {
        k_hist<<<2048, 256>>>(level);
        k_scan<<<1, 256>>>(level);
    }
    k_main<<<dim3(N/ROWS_PB, JSPLIT), dim3(16, 16)>>>();
    k_epilogue<<<N, 32>>>(x, out);
}